// round 8
// baseline (speedup 1.0000x reference)
#include <cuda_runtime.h>

// GraphSage 2-layer, fp32. N=50000, E=600000, D=128, DOUT=64.
// CSR-based aggregation (built once per call, used by both layers):
//   prep(zero cnt) -> count -> scan -> fill -> gather1 -> GEMM1(relu) -> gather2 -> GEMM2

#define N_NODES 50000
#define N_EDGES 600000
#define D       128
#define DOUT    64

__device__ float g_bufA[N_NODES * D];     // gathered mean (both layers)
__device__ float g_bufB[N_NODES * D];     // h = layer-1 output
__device__ int   g_deg[N_NODES];
__device__ int   g_base[N_NODES];
__device__ int   g_cursor[N_NODES];
__device__ int   g_csr[N_EDGES];          // src indices grouped by dst
__device__ float g_Wc1[2 * D * D];        // [256][128] k-major: rows 0..127=W1l^T, 128..255=W1r^T
__device__ float g_Wc2[2 * D * DOUT];     // [256][64]

// ---------------------------------------------------------------------------
// Pack weights k-major + zero per-call counters.
__global__ void prep_weights(const float* __restrict__ W1l, const float* __restrict__ W1r,
                             const float* __restrict__ W2l, const float* __restrict__ W2r)
{
    int i = blockIdx.x * blockDim.x + threadIdx.x;
    if (i < 2 * D * D) {
        int k = i / D, n = i % D;
        g_Wc1[i] = (k < D) ? W1l[n * D + k] : W1r[n * D + (k - D)];
    }
    if (i < 2 * D * DOUT) {
        int k = i / DOUT, n = i % DOUT;
        g_Wc2[i] = (k < D) ? W2l[n * D + k] : W2r[n * D + (k - D)];
    }
    if (i < N_NODES) {
        g_deg[i] = 0;
        g_cursor[i] = 0;
    }
}

// ---------------------------------------------------------------------------
__global__ void count_kernel(const int* __restrict__ ei)
{
    int e = blockIdx.x * blockDim.x + threadIdx.x;
    if (e < N_EDGES)
        atomicAdd(g_deg + __ldg(ei + N_EDGES + e), 1);
}

// ---------------------------------------------------------------------------
// Exclusive scan of g_deg into g_base. One block, 1024 threads, chunked.
__global__ void scan_kernel()
{
    __shared__ int part[1024];
    const int CH = (N_NODES + 1023) / 1024;   // 49
    int t = threadIdx.x;
    int s = 0;
    int b0 = t * CH;
#pragma unroll 4
    for (int i = 0; i < CH; i++) {
        int idx = b0 + i;
        if (idx < N_NODES) s += g_deg[idx];
    }
    part[t] = s;
    __syncthreads();
    for (int off = 1; off < 1024; off <<= 1) {
        int tmp = (t >= off) ? part[t - off] : 0;
        __syncthreads();
        part[t] += tmp;
        __syncthreads();
    }
    int running = part[t] - s;                 // exclusive prefix
    for (int i = 0; i < CH; i++) {
        int idx = b0 + i;
        if (idx < N_NODES) {
            g_base[idx] = running;
            running += g_deg[idx];
        }
    }
}

// ---------------------------------------------------------------------------
__global__ void fill_kernel(const int* __restrict__ ei)
{
    int e = blockIdx.x * blockDim.x + threadIdx.x;
    if (e >= N_EDGES) return;
    int src = __ldg(ei + e);
    int dst = __ldg(ei + N_EDGES + e);
    int pos = g_base[dst] + atomicAdd(g_cursor + dst, 1);
    g_csr[pos] = src;
}

// ---------------------------------------------------------------------------
// One warp per node: gather neighbor rows, mean, write g_bufA. No atomics.
__global__ void gather_kernel(const float4* __restrict__ xfeat, int layer)
{
    int n = blockIdx.x * 8 + (threadIdx.x >> 5);
    if (n >= N_NODES) return;
    int lane = threadIdx.x & 31;
    const float4* feat = layer ? reinterpret_cast<const float4*>(g_bufB) : xfeat;
    int beg = g_base[n];
    int d = g_deg[n];
    float4 acc = make_float4(0.f, 0.f, 0.f, 0.f);
    int i = 0;
    for (; i + 4 <= d; i += 4) {
        int s0 = __ldg(g_csr + beg + i);
        int s1 = __ldg(g_csr + beg + i + 1);
        int s2 = __ldg(g_csr + beg + i + 2);
        int s3 = __ldg(g_csr + beg + i + 3);
        float4 v0 = feat[s0 * 32 + lane];
        float4 v1 = feat[s1 * 32 + lane];
        float4 v2 = feat[s2 * 32 + lane];
        float4 v3 = feat[s3 * 32 + lane];
        acc.x += (v0.x + v1.x) + (v2.x + v3.x);
        acc.y += (v0.y + v1.y) + (v2.y + v3.y);
        acc.z += (v0.z + v1.z) + (v2.z + v3.z);
        acc.w += (v0.w + v1.w) + (v2.w + v3.w);
    }
    for (; i < d; i++) {
        int s = __ldg(g_csr + beg + i);
        float4 v = feat[s * 32 + lane];
        acc.x += v.x; acc.y += v.y; acc.z += v.z; acc.w += v.w;
    }
    float sc = 1.0f / fmaxf((float)d, 1.0f);
    acc.x *= sc; acc.y *= sc; acc.z *= sc; acc.w *= sc;
    reinterpret_cast<float4*>(g_bufA)[n * 32 + lane] = acc;
}

// ---------------------------------------------------------------------------
// Fused SAGE GEMM:  C[r][n] = act( bias[n] + sum_k A_concat[r][k] * Wc[k][n] )
// A_concat[r][k] = (k<128) ? g_bufA[r][k] (pre-meaned) : Aself[r][k-128]
// Inner product via packed fma.rn.f32x2 (2 MACs/instr).
template<int BN, int TN, bool RELU, bool LAYER2>
__global__ void __launch_bounds__(256, 2) sage_gemm(const float* __restrict__ Aself_in,
                                                    const float* __restrict__ bias,
                                                    float* __restrict__ Cout)
{
    constexpr int BM = 128, BK = 16, TM = 8;
    constexpr int CT = BN / TN;                 // 16 in both configs
    constexpr int TN2 = TN / 2;
    __shared__ float As[BK][BM + 4];
    __shared__ float Ws[BK][BN];

    const float* Aagg  = g_bufA;
    const float* Aself = LAYER2 ? g_bufB : Aself_in;
    const float* Wc    = LAYER2 ? g_Wc2 : g_Wc1;
    float*       C     = LAYER2 ? Cout  : g_bufB;

    int tid = threadIdx.x;
    int tx = tid % CT;
    int ty = tid / CT;
    int rowBase = blockIdx.x * BM;

    unsigned long long acc2[TM][TN2];
#pragma unroll
    for (int j2 = 0; j2 < TN2; j2++) {
        float blo = bias[tx * TN + 2 * j2];
        float bhi = bias[tx * TN + 2 * j2 + 1];
        unsigned long long b2;
        asm("mov.b64 %0, {%1, %2};" : "=l"(b2) : "f"(blo), "f"(bhi));
#pragma unroll
        for (int i = 0; i < TM; i++)
            acc2[i][j2] = b2;
    }

    int lr = tid >> 2;
    int kk0 = (tid & 3) * 4;
    int r0 = rowBase + lr;
    int r1 = rowBase + lr + 64;
    bool v0 = r0 < N_NODES, v1 = r1 < N_NODES;

    for (int kt = 0; kt < (2 * D) / BK; kt++) {
        int kglob = kt * BK + kk0;
        bool aggpart = kglob < D;               // BK=16 divides 128: whole tile on one side
        {
            float4 va = make_float4(0.f, 0.f, 0.f, 0.f);
            if (v0) {
                const float* b = aggpart ? (Aagg + r0 * D + kglob)
                                         : (Aself + r0 * D + (kglob - D));
                va = *reinterpret_cast<const float4*>(b);
            }
            As[kk0 + 0][lr] = va.x; As[kk0 + 1][lr] = va.y;
            As[kk0 + 2][lr] = va.z; As[kk0 + 3][lr] = va.w;
        }
        {
            float4 va = make_float4(0.f, 0.f, 0.f, 0.f);
            if (v1) {
                const float* b = aggpart ? (Aagg + r1 * D + kglob)
                                         : (Aself + r1 * D + (kglob - D));
                va = *reinterpret_cast<const float4*>(b);
            }
            As[kk0 + 0][lr + 64] = va.x; As[kk0 + 1][lr + 64] = va.y;
            As[kk0 + 2][lr + 64] = va.z; As[kk0 + 3][lr + 64] = va.w;
        }
#pragma unroll
        for (int idx = tid * 4; idx < BK * BN; idx += 256 * 4) {
            int kk = idx / BN, c = idx % BN;
            *reinterpret_cast<float4*>(&Ws[kk][c]) =
                *reinterpret_cast<const float4*>(&Wc[(kt * BK + kk) * BN + c]);
        }
        __syncthreads();

#pragma unroll
        for (int kk = 0; kk < BK; kk++) {
            float a[TM];
            unsigned long long w2[TN2];
#pragma unroll
            for (int i = 0; i < TM; i += 4)
                *reinterpret_cast<float4*>(&a[i]) =
                    *reinterpret_cast<const float4*>(&As[kk][ty * TM + i]);
#pragma unroll
            for (int j2 = 0; j2 < TN2; j2 += 2) {
                float4 wv = *reinterpret_cast<const float4*>(&Ws[kk][tx * TN + 2 * j2]);
                w2[j2]     = *reinterpret_cast<unsigned long long*>(&wv.x);
                w2[j2 + 1] = *reinterpret_cast<unsigned long long*>(&wv.z);
            }
#pragma unroll
            for (int i = 0; i < TM; i++) {
                unsigned long long a2;
                asm("mov.b64 %0, {%1, %1};" : "=l"(a2) : "f"(a[i]));
#pragma unroll
                for (int j2 = 0; j2 < TN2; j2++)
                    asm("fma.rn.f32x2 %0, %1, %2, %0;"
                        : "+l"(acc2[i][j2]) : "l"(a2), "l"(w2[j2]));
            }
        }
        __syncthreads();
    }

#pragma unroll
    for (int i = 0; i < TM; i++) {
        int r = rowBase + ty * TM + i;
        if (r < N_NODES) {
#pragma unroll
            for (int j2 = 0; j2 < TN2; j2 += 2) {
                float2 p0 = *reinterpret_cast<float2*>(&acc2[i][j2]);
                float2 p1 = *reinterpret_cast<float2*>(&acc2[i][j2 + 1]);
                float4 o;
                o.x = RELU ? fmaxf(p0.x, 0.f) : p0.x;
                o.y = RELU ? fmaxf(p0.y, 0.f) : p0.y;
                o.z = RELU ? fmaxf(p1.x, 0.f) : p1.x;
                o.w = RELU ? fmaxf(p1.y, 0.f) : p1.y;
                *reinterpret_cast<float4*>(&C[r * BN + tx * TN + 2 * j2]) = o;
            }
        }
    }
}

// ---------------------------------------------------------------------------
extern "C" void kernel_launch(void* const* d_in, const int* in_sizes, int n_in,
                              void* d_out, int out_size)
{
    const float* x   = (const float*)d_in[0];
    const int*   ei  = (const int*)  d_in[1];
    const float* W1l = (const float*)d_in[2];
    const float* b1  = (const float*)d_in[3];
    const float* W1r = (const float*)d_in[4];
    const float* W2l = (const float*)d_in[5];
    const float* b2  = (const float*)d_in[6];
    const float* W2r = (const float*)d_in[7];
    float* out = (float*)d_out;

    const int egrid = (N_EDGES + 255) / 256;
    const int ngrid = (N_NODES + 7) / 8;        // gather: warp per node
    const int ggrid = (N_NODES + 127) / 128;    // 391

    prep_weights<<<(N_NODES + 255) / 256, 256>>>(W1l, W1r, W2l, W2r);
    count_kernel<<<egrid, 256>>>(ei);
    scan_kernel<<<1, 1024>>>();
    fill_kernel<<<egrid, 256>>>(ei);
    gather_kernel<<<ngrid, 256>>>((const float4*)x, 0);
    sage_gemm<128, 8, true,  false><<<ggrid, 256>>>(x, b1, nullptr);
    gather_kernel<<<ngrid, 256>>>((const float4*)x, 1);
    sage_gemm<64, 4, false, true><<<ggrid, 256>>>(nullptr, b2, out);
}

// round 9
// speedup vs baseline: 1.0028x; 1.0028x over previous
#include <cuda_runtime.h>

// GraphSage 2-layer, fp32. N=50000, E=600000, D=128, DOUT=64.
// CSR-based aggregation (built once per call, used by both layers):
//   prep(zero cnt) -> count -> scan -> fill -> gather1 -> GEMM1(relu) -> gather2 -> GEMM2

#define N_NODES 50000
#define N_EDGES 600000
#define D       128
#define DOUT    64

__device__ float g_bufA[N_NODES * D];     // gathered mean (both layers)
__device__ float g_bufB[N_NODES * D];     // h = layer-1 output
__device__ int   g_deg[N_NODES];
__device__ int   g_base[N_NODES];
__device__ int   g_cursor[N_NODES];
__device__ int   g_csr[N_EDGES];          // src indices grouped by dst
__device__ float g_Wc1[2 * D * D];        // [256][128] k-major: rows 0..127=W1l^T, 128..255=W1r^T
__device__ float g_Wc2[2 * D * DOUT];     // [256][64]

// ---------------------------------------------------------------------------
// Pack weights k-major + zero per-call counters.
__global__ void prep_weights(const float* __restrict__ W1l, const float* __restrict__ W1r,
                             const float* __restrict__ W2l, const float* __restrict__ W2r)
{
    int i = blockIdx.x * blockDim.x + threadIdx.x;
    if (i < 2 * D * D) {
        int k = i / D, n = i % D;
        g_Wc1[i] = (k < D) ? W1l[n * D + k] : W1r[n * D + (k - D)];
    }
    if (i < 2 * D * DOUT) {
        int k = i / DOUT, n = i % DOUT;
        g_Wc2[i] = (k < D) ? W2l[n * D + k] : W2r[n * D + (k - D)];
    }
    if (i < N_NODES) {
        g_deg[i] = 0;
        g_cursor[i] = 0;
    }
}

// ---------------------------------------------------------------------------
__global__ void count_kernel(const int* __restrict__ ei)
{
    int e = blockIdx.x * blockDim.x + threadIdx.x;
    if (e < N_EDGES)
        atomicAdd(g_deg + __ldg(ei + N_EDGES + e), 1);
}

// ---------------------------------------------------------------------------
// Exclusive scan of g_deg into g_base. One block, 1024 threads, chunked.
__global__ void scan_kernel()
{
    __shared__ int part[1024];
    const int CH = (N_NODES + 1023) / 1024;   // 49
    int t = threadIdx.x;
    int s = 0;
    int b0 = t * CH;
#pragma unroll 4
    for (int i = 0; i < CH; i++) {
        int idx = b0 + i;
        if (idx < N_NODES) s += g_deg[idx];
    }
    part[t] = s;
    __syncthreads();
    for (int off = 1; off < 1024; off <<= 1) {
        int tmp = (t >= off) ? part[t - off] : 0;
        __syncthreads();
        part[t] += tmp;
        __syncthreads();
    }
    int running = part[t] - s;                 // exclusive prefix
    for (int i = 0; i < CH; i++) {
        int idx = b0 + i;
        if (idx < N_NODES) {
            g_base[idx] = running;
            running += g_deg[idx];
        }
    }
}

// ---------------------------------------------------------------------------
__global__ void fill_kernel(const int* __restrict__ ei)
{
    int e = blockIdx.x * blockDim.x + threadIdx.x;
    if (e >= N_EDGES) return;
    int src = __ldg(ei + e);
    int dst = __ldg(ei + N_EDGES + e);
    int pos = g_base[dst] + atomicAdd(g_cursor + dst, 1);
    g_csr[pos] = src;
}

// ---------------------------------------------------------------------------
// One warp per node: gather neighbor rows, mean, write g_bufA. No atomics.
__global__ void gather_kernel(const float4* __restrict__ xfeat, int layer)
{
    int n = blockIdx.x * 8 + (threadIdx.x >> 5);
    if (n >= N_NODES) return;
    int lane = threadIdx.x & 31;
    const float4* feat = layer ? reinterpret_cast<const float4*>(g_bufB) : xfeat;
    int beg = g_base[n];
    int d = g_deg[n];
    float4 acc = make_float4(0.f, 0.f, 0.f, 0.f);
    int i = 0;
    for (; i + 4 <= d; i += 4) {
        int s0 = __ldg(g_csr + beg + i);
        int s1 = __ldg(g_csr + beg + i + 1);
        int s2 = __ldg(g_csr + beg + i + 2);
        int s3 = __ldg(g_csr + beg + i + 3);
        float4 v0 = feat[s0 * 32 + lane];
        float4 v1 = feat[s1 * 32 + lane];
        float4 v2 = feat[s2 * 32 + lane];
        float4 v3 = feat[s3 * 32 + lane];
        acc.x += (v0.x + v1.x) + (v2.x + v3.x);
        acc.y += (v0.y + v1.y) + (v2.y + v3.y);
        acc.z += (v0.z + v1.z) + (v2.z + v3.z);
        acc.w += (v0.w + v1.w) + (v2.w + v3.w);
    }
    for (; i < d; i++) {
        int s = __ldg(g_csr + beg + i);
        float4 v = feat[s * 32 + lane];
        acc.x += v.x; acc.y += v.y; acc.z += v.z; acc.w += v.w;
    }
    float sc = 1.0f / fmaxf((float)d, 1.0f);
    acc.x *= sc; acc.y *= sc; acc.z *= sc; acc.w *= sc;
    reinterpret_cast<float4*>(g_bufA)[n * 32 + lane] = acc;
}

// ---------------------------------------------------------------------------
// Fused SAGE GEMM:  C[r][n] = act( bias[n] + sum_k A_concat[r][k] * Wc[k][n] )
// A_concat[r][k] = (k<128) ? g_bufA[r][k] (pre-meaned) : Aself[r][k-128]
// Inner product via packed fma.rn.f32x2 (2 MACs/instr).
template<int BN, int TN, bool RELU, bool LAYER2>
__global__ void __launch_bounds__(256, 2) sage_gemm(const float* __restrict__ Aself_in,
                                                    const float* __restrict__ bias,
                                                    float* __restrict__ Cout)
{
    constexpr int BM = 128, BK = 16, TM = 8;
    constexpr int CT = BN / TN;                 // 16 in both configs
    constexpr int TN2 = TN / 2;
    __shared__ float As[BK][BM + 4];
    __shared__ float Ws[BK][BN];

    const float* Aagg  = g_bufA;
    const float* Aself = LAYER2 ? g_bufB : Aself_in;
    const float* Wc    = LAYER2 ? g_Wc2 : g_Wc1;
    float*       C     = LAYER2 ? Cout  : g_bufB;

    int tid = threadIdx.x;
    int tx = tid % CT;
    int ty = tid / CT;
    int rowBase = blockIdx.x * BM;

    unsigned long long acc2[TM][TN2];
#pragma unroll
    for (int j2 = 0; j2 < TN2; j2++) {
        float blo = bias[tx * TN + 2 * j2];
        float bhi = bias[tx * TN + 2 * j2 + 1];
        unsigned long long b2;
        asm("mov.b64 %0, {%1, %2};" : "=l"(b2) : "f"(blo), "f"(bhi));
#pragma unroll
        for (int i = 0; i < TM; i++)
            acc2[i][j2] = b2;
    }

    int lr = tid >> 2;
    int kk0 = (tid & 3) * 4;
    int r0 = rowBase + lr;
    int r1 = rowBase + lr + 64;
    bool v0 = r0 < N_NODES, v1 = r1 < N_NODES;

    for (int kt = 0; kt < (2 * D) / BK; kt++) {
        int kglob = kt * BK + kk0;
        bool aggpart = kglob < D;               // BK=16 divides 128: whole tile on one side
        {
            float4 va = make_float4(0.f, 0.f, 0.f, 0.f);
            if (v0) {
                const float* b = aggpart ? (Aagg + r0 * D + kglob)
                                         : (Aself + r0 * D + (kglob - D));
                va = *reinterpret_cast<const float4*>(b);
            }
            As[kk0 + 0][lr] = va.x; As[kk0 + 1][lr] = va.y;
            As[kk0 + 2][lr] = va.z; As[kk0 + 3][lr] = va.w;
        }
        {
            float4 va = make_float4(0.f, 0.f, 0.f, 0.f);
            if (v1) {
                const float* b = aggpart ? (Aagg + r1 * D + kglob)
                                         : (Aself + r1 * D + (kglob - D));
                va = *reinterpret_cast<const float4*>(b);
            }
            As[kk0 + 0][lr + 64] = va.x; As[kk0 + 1][lr + 64] = va.y;
            As[kk0 + 2][lr + 64] = va.z; As[kk0 + 3][lr + 64] = va.w;
        }
#pragma unroll
        for (int idx = tid * 4; idx < BK * BN; idx += 256 * 4) {
            int kk = idx / BN, c = idx % BN;
            *reinterpret_cast<float4*>(&Ws[kk][c]) =
                *reinterpret_cast<const float4*>(&Wc[(kt * BK + kk) * BN + c]);
        }
        __syncthreads();

#pragma unroll
        for (int kk = 0; kk < BK; kk++) {
            float a[TM];
            unsigned long long w2[TN2];
#pragma unroll
            for (int i = 0; i < TM; i += 4)
                *reinterpret_cast<float4*>(&a[i]) =
                    *reinterpret_cast<const float4*>(&As[kk][ty * TM + i]);
#pragma unroll
            for (int j2 = 0; j2 < TN2; j2 += 2) {
                float4 wv = *reinterpret_cast<const float4*>(&Ws[kk][tx * TN + 2 * j2]);
                w2[j2]     = *reinterpret_cast<unsigned long long*>(&wv.x);
                w2[j2 + 1] = *reinterpret_cast<unsigned long long*>(&wv.z);
            }
#pragma unroll
            for (int i = 0; i < TM; i++) {
                unsigned long long a2;
                asm("mov.b64 %0, {%1, %1};" : "=l"(a2) : "f"(a[i]));
#pragma unroll
                for (int j2 = 0; j2 < TN2; j2++)
                    asm("fma.rn.f32x2 %0, %1, %2, %0;"
                        : "+l"(acc2[i][j2]) : "l"(a2), "l"(w2[j2]));
            }
        }
        __syncthreads();
    }

#pragma unroll
    for (int i = 0; i < TM; i++) {
        int r = rowBase + ty * TM + i;
        if (r < N_NODES) {
#pragma unroll
            for (int j2 = 0; j2 < TN2; j2 += 2) {
                float2 p0 = *reinterpret_cast<float2*>(&acc2[i][j2]);
                float2 p1 = *reinterpret_cast<float2*>(&acc2[i][j2 + 1]);
                float4 o;
                o.x = RELU ? fmaxf(p0.x, 0.f) : p0.x;
                o.y = RELU ? fmaxf(p0.y, 0.f) : p0.y;
                o.z = RELU ? fmaxf(p1.x, 0.f) : p1.x;
                o.w = RELU ? fmaxf(p1.y, 0.f) : p1.y;
                *reinterpret_cast<float4*>(&C[r * BN + tx * TN + 2 * j2]) = o;
            }
        }
    }
}

// ---------------------------------------------------------------------------
extern "C" void kernel_launch(void* const* d_in, const int* in_sizes, int n_in,
                              void* d_out, int out_size)
{
    const float* x   = (const float*)d_in[0];
    const int*   ei  = (const int*)  d_in[1];
    const float* W1l = (const float*)d_in[2];
    const float* b1  = (const float*)d_in[3];
    const float* W1r = (const float*)d_in[4];
    const float* W2l = (const float*)d_in[5];
    const float* b2  = (const float*)d_in[6];
    const float* W2r = (const float*)d_in[7];
    float* out = (float*)d_out;

    const int egrid = (N_EDGES + 255) / 256;
    const int ngrid = (N_NODES + 7) / 8;        // gather: warp per node
    const int ggrid = (N_NODES + 127) / 128;    // 391

    prep_weights<<<(N_NODES + 255) / 256, 256>>>(W1l, W1r, W2l, W2r);
    count_kernel<<<egrid, 256>>>(ei);
    scan_kernel<<<1, 1024>>>();
    fill_kernel<<<egrid, 256>>>(ei);
    gather_kernel<<<ngrid, 256>>>((const float4*)x, 0);
    sage_gemm<128, 8, true,  false><<<ggrid, 256>>>(x, b1, nullptr);
    gather_kernel<<<ngrid, 256>>>((const float4*)x, 1);
    sage_gemm<64, 4, false, true><<<ggrid, 256>>>(nullptr, b2, out);
}

// round 10
// speedup vs baseline: 1.0039x; 1.0011x over previous
#include <cuda_runtime.h>

// GraphSage 2-layer, fp32. N=50000, E=600000, D=128, DOUT=64.
// CSR-based aggregation (built once per call, used by both layers):
//   prep(zero cnt) -> count -> scan -> fill -> gather1 -> GEMM1(relu) -> gather2 -> GEMM2

#define N_NODES 50000
#define N_EDGES 600000
#define D       128
#define DOUT    64

__device__ float g_bufA[N_NODES * D];     // gathered mean (both layers)
__device__ float g_bufB[N_NODES * D];     // h = layer-1 output
__device__ int   g_deg[N_NODES];
__device__ int   g_base[N_NODES];
__device__ int   g_cursor[N_NODES];
__device__ int   g_csr[N_EDGES];          // src indices grouped by dst
__device__ float g_Wc1[2 * D * D];        // [256][128] k-major: rows 0..127=W1l^T, 128..255=W1r^T
__device__ float g_Wc2[2 * D * DOUT];     // [256][64]

// ---------------------------------------------------------------------------
// Pack weights k-major + zero per-call counters.
__global__ void prep_weights(const float* __restrict__ W1l, const float* __restrict__ W1r,
                             const float* __restrict__ W2l, const float* __restrict__ W2r)
{
    int i = blockIdx.x * blockDim.x + threadIdx.x;
    if (i < 2 * D * D) {
        int k = i / D, n = i % D;
        g_Wc1[i] = (k < D) ? W1l[n * D + k] : W1r[n * D + (k - D)];
    }
    if (i < 2 * D * DOUT) {
        int k = i / DOUT, n = i % DOUT;
        g_Wc2[i] = (k < D) ? W2l[n * D + k] : W2r[n * D + (k - D)];
    }
    if (i < N_NODES) {
        g_deg[i] = 0;
        g_cursor[i] = 0;
    }
}

// ---------------------------------------------------------------------------
__global__ void count_kernel(const int* __restrict__ ei)
{
    int e = blockIdx.x * blockDim.x + threadIdx.x;
    if (e < N_EDGES)
        atomicAdd(g_deg + __ldg(ei + N_EDGES + e), 1);
}

// ---------------------------------------------------------------------------
// Exclusive scan of g_deg into g_base. One block, 1024 threads, chunked.
__global__ void scan_kernel()
{
    __shared__ int part[1024];
    const int CH = (N_NODES + 1023) / 1024;   // 49
    int t = threadIdx.x;
    int s = 0;
    int b0 = t * CH;
#pragma unroll 4
    for (int i = 0; i < CH; i++) {
        int idx = b0 + i;
        if (idx < N_NODES) s += g_deg[idx];
    }
    part[t] = s;
    __syncthreads();
    for (int off = 1; off < 1024; off <<= 1) {
        int tmp = (t >= off) ? part[t - off] : 0;
        __syncthreads();
        part[t] += tmp;
        __syncthreads();
    }
    int running = part[t] - s;                 // exclusive prefix
    for (int i = 0; i < CH; i++) {
        int idx = b0 + i;
        if (idx < N_NODES) {
            g_base[idx] = running;
            running += g_deg[idx];
        }
    }
}

// ---------------------------------------------------------------------------
__global__ void fill_kernel(const int* __restrict__ ei)
{
    int e = blockIdx.x * blockDim.x + threadIdx.x;
    if (e >= N_EDGES) return;
    int src = __ldg(ei + e);
    int dst = __ldg(ei + N_EDGES + e);
    int pos = g_base[dst] + atomicAdd(g_cursor + dst, 1);
    g_csr[pos] = src;
}

// ---------------------------------------------------------------------------
// One warp per node: gather neighbor rows, mean, write g_bufA. No atomics.
__global__ void gather_kernel(const float4* __restrict__ xfeat, int layer)
{
    int n = blockIdx.x * 8 + (threadIdx.x >> 5);
    if (n >= N_NODES) return;
    int lane = threadIdx.x & 31;
    const float4* feat = layer ? reinterpret_cast<const float4*>(g_bufB) : xfeat;
    int beg = g_base[n];
    int d = g_deg[n];
    float4 acc = make_float4(0.f, 0.f, 0.f, 0.f);
    int i = 0;
    for (; i + 4 <= d; i += 4) {
        int s0 = __ldg(g_csr + beg + i);
        int s1 = __ldg(g_csr + beg + i + 1);
        int s2 = __ldg(g_csr + beg + i + 2);
        int s3 = __ldg(g_csr + beg + i + 3);
        float4 v0 = feat[s0 * 32 + lane];
        float4 v1 = feat[s1 * 32 + lane];
        float4 v2 = feat[s2 * 32 + lane];
        float4 v3 = feat[s3 * 32 + lane];
        acc.x += (v0.x + v1.x) + (v2.x + v3.x);
        acc.y += (v0.y + v1.y) + (v2.y + v3.y);
        acc.z += (v0.z + v1.z) + (v2.z + v3.z);
        acc.w += (v0.w + v1.w) + (v2.w + v3.w);
    }
    for (; i < d; i++) {
        int s = __ldg(g_csr + beg + i);
        float4 v = feat[s * 32 + lane];
        acc.x += v.x; acc.y += v.y; acc.z += v.z; acc.w += v.w;
    }
    float sc = 1.0f / fmaxf((float)d, 1.0f);
    acc.x *= sc; acc.y *= sc; acc.z *= sc; acc.w *= sc;
    reinterpret_cast<float4*>(g_bufA)[n * 32 + lane] = acc;
}

// ---------------------------------------------------------------------------
// Fused SAGE GEMM:  C[r][n] = act( bias[n] + sum_k A_concat[r][k] * Wc[k][n] )
// A_concat[r][k] = (k<128) ? g_bufA[r][k] (pre-meaned) : Aself[r][k-128]
// Inner product via packed fma.rn.f32x2 (2 MACs/instr).
template<int BN, int TN, bool RELU, bool LAYER2>
__global__ void __launch_bounds__(256, 2) sage_gemm(const float* __restrict__ Aself_in,
                                                    const float* __restrict__ bias,
                                                    float* __restrict__ Cout)
{
    constexpr int BM = 128, BK = 16, TM = 8;
    constexpr int CT = BN / TN;                 // 16 in both configs
    constexpr int TN2 = TN / 2;
    __shared__ float As[BK][BM + 4];
    __shared__ float Ws[BK][BN];

    const float* Aagg  = g_bufA;
    const float* Aself = LAYER2 ? g_bufB : Aself_in;
    const float* Wc    = LAYER2 ? g_Wc2 : g_Wc1;
    float*       C     = LAYER2 ? Cout  : g_bufB;

    int tid = threadIdx.x;
    int tx = tid % CT;
    int ty = tid / CT;
    int rowBase = blockIdx.x * BM;

    unsigned long long acc2[TM][TN2];
#pragma unroll
    for (int j2 = 0; j2 < TN2; j2++) {
        float blo = bias[tx * TN + 2 * j2];
        float bhi = bias[tx * TN + 2 * j2 + 1];
        unsigned long long b2;
        asm("mov.b64 %0, {%1, %2};" : "=l"(b2) : "f"(blo), "f"(bhi));
#pragma unroll
        for (int i = 0; i < TM; i++)
            acc2[i][j2] = b2;
    }

    int lr = tid >> 2;
    int kk0 = (tid & 3) * 4;
    int r0 = rowBase + lr;
    int r1 = rowBase + lr + 64;
    bool v0 = r0 < N_NODES, v1 = r1 < N_NODES;

    for (int kt = 0; kt < (2 * D) / BK; kt++) {
        int kglob = kt * BK + kk0;
        bool aggpart = kglob < D;               // BK=16 divides 128: whole tile on one side
        {
            float4 va = make_float4(0.f, 0.f, 0.f, 0.f);
            if (v0) {
                const float* b = aggpart ? (Aagg + r0 * D + kglob)
                                         : (Aself + r0 * D + (kglob - D));
                va = *reinterpret_cast<const float4*>(b);
            }
            As[kk0 + 0][lr] = va.x; As[kk0 + 1][lr] = va.y;
            As[kk0 + 2][lr] = va.z; As[kk0 + 3][lr] = va.w;
        }
        {
            float4 va = make_float4(0.f, 0.f, 0.f, 0.f);
            if (v1) {
                const float* b = aggpart ? (Aagg + r1 * D + kglob)
                                         : (Aself + r1 * D + (kglob - D));
                va = *reinterpret_cast<const float4*>(b);
            }
            As[kk0 + 0][lr + 64] = va.x; As[kk0 + 1][lr + 64] = va.y;
            As[kk0 + 2][lr + 64] = va.z; As[kk0 + 3][lr + 64] = va.w;
        }
#pragma unroll
        for (int idx = tid * 4; idx < BK * BN; idx += 256 * 4) {
            int kk = idx / BN, c = idx % BN;
            *reinterpret_cast<float4*>(&Ws[kk][c]) =
                *reinterpret_cast<const float4*>(&Wc[(kt * BK + kk) * BN + c]);
        }
        __syncthreads();

#pragma unroll
        for (int kk = 0; kk < BK; kk++) {
            float a[TM];
            unsigned long long w2[TN2];
#pragma unroll
            for (int i = 0; i < TM; i += 4)
                *reinterpret_cast<float4*>(&a[i]) =
                    *reinterpret_cast<const float4*>(&As[kk][ty * TM + i]);
#pragma unroll
            for (int j2 = 0; j2 < TN2; j2 += 2) {
                float4 wv = *reinterpret_cast<const float4*>(&Ws[kk][tx * TN + 2 * j2]);
                w2[j2]     = *reinterpret_cast<unsigned long long*>(&wv.x);
                w2[j2 + 1] = *reinterpret_cast<unsigned long long*>(&wv.z);
            }
#pragma unroll
            for (int i = 0; i < TM; i++) {
                unsigned long long a2;
                asm("mov.b64 %0, {%1, %1};" : "=l"(a2) : "f"(a[i]));
#pragma unroll
                for (int j2 = 0; j2 < TN2; j2++)
                    asm("fma.rn.f32x2 %0, %1, %2, %0;"
                        : "+l"(acc2[i][j2]) : "l"(a2), "l"(w2[j2]));
            }
        }
        __syncthreads();
    }

#pragma unroll
    for (int i = 0; i < TM; i++) {
        int r = rowBase + ty * TM + i;
        if (r < N_NODES) {
#pragma unroll
            for (int j2 = 0; j2 < TN2; j2 += 2) {
                float2 p0 = *reinterpret_cast<float2*>(&acc2[i][j2]);
                float2 p1 = *reinterpret_cast<float2*>(&acc2[i][j2 + 1]);
                float4 o;
                o.x = RELU ? fmaxf(p0.x, 0.f) : p0.x;
                o.y = RELU ? fmaxf(p0.y, 0.f) : p0.y;
                o.z = RELU ? fmaxf(p1.x, 0.f) : p1.x;
                o.w = RELU ? fmaxf(p1.y, 0.f) : p1.y;
                *reinterpret_cast<float4*>(&C[r * BN + tx * TN + 2 * j2]) = o;
            }
        }
    }
}

// ---------------------------------------------------------------------------
extern "C" void kernel_launch(void* const* d_in, const int* in_sizes, int n_in,
                              void* d_out, int out_size)
{
    const float* x   = (const float*)d_in[0];
    const int*   ei  = (const int*)  d_in[1];
    const float* W1l = (const float*)d_in[2];
    const float* b1  = (const float*)d_in[3];
    const float* W1r = (const float*)d_in[4];
    const float* W2l = (const float*)d_in[5];
    const float* b2  = (const float*)d_in[6];
    const float* W2r = (const float*)d_in[7];
    float* out = (float*)d_out;

    const int egrid = (N_EDGES + 255) / 256;
    const int ngrid = (N_NODES + 7) / 8;        // gather: warp per node
    const int ggrid = (N_NODES + 127) / 128;    // 391

    prep_weights<<<(N_NODES + 255) / 256, 256>>>(W1l, W1r, W2l, W2r);
    count_kernel<<<egrid, 256>>>(ei);
    scan_kernel<<<1, 1024>>>();
    fill_kernel<<<egrid, 256>>>(ei);
    gather_kernel<<<ngrid, 256>>>((const float4*)x, 0);
    sage_gemm<128, 8, true,  false><<<ggrid, 256>>>(x, b1, nullptr);
    gather_kernel<<<ngrid, 256>>>((const float4*)x, 1);
    sage_gemm<64, 4, false, true><<<ggrid, 256>>>(nullptr, b2, out);
}